// round 2
// baseline (speedup 1.0000x reference)
#include <cuda_runtime.h>
#include <cstdint>

#define NN 100000
#define EE 3200000
#define FC 32
#define FULLMASK 0xFFFFFFFFu

// ---------------- scratch (device globals; no allocation anywhere) ----------
__device__ int   g_is64;
__device__ int   g_row[EE];
__device__ int   g_col[EE];
__device__ int   g_deg[NN];
__device__ float g_dinv[NN];
__device__ int   g_indptr[NN + 1];
__device__ int   g_pos[NN];
__device__ int   g_ccsr[EE];
__device__ float g_wcsr[EE];
__device__ int   g_partials[512];

__device__ float g_tx1all[24 * NN * 4];   // layer1 Chebyshev basis, float4-padded
__device__ float g_bufA[NN * FC];
__device__ float g_bufB[NN * FC];
__device__ float g_bufC[NN * FC];
__device__ float g_bufD[NN * FC];

__device__ __forceinline__ float* selbuf(int s) {
    switch (s) {
        case 0:  return g_bufA;
        case 1:  return g_bufB;
        case 2:  return g_bufC;
        default: return g_bufD;
    }
}

__device__ __forceinline__ float silu(float x) {
    return x / (1.f + __expf(-x));
}

// ---------------- dtype detection -------------------------------------------
// If edge_index is int64 (little-endian, values < 2^31), every odd int32 word
// of the first entries is 0. If it is int32, odd words are random node ids.
__global__ void k_detect(const int* __restrict__ ei32) {
    if (threadIdx.x == 0) {
        int is64 = 1;
        for (int i = 0; i < 512; i++) {
            if (ei32[2 * i + 1] != 0) { is64 = 0; break; }
        }
        g_is64 = is64;
    }
}

// ---------------- graph preprocessing ---------------------------------------
__global__ void k_zero_deg() {
    int i = blockIdx.x * blockDim.x + threadIdx.x;
    if (i < NN) g_deg[i] = 0;
}

__global__ void k_edges(const void* __restrict__ eiv) {
    int e = blockIdx.x * blockDim.x + threadIdx.x;
    if (e >= EE) return;
    int r, c;
    if (g_is64) {
        const long long* ei = (const long long*)eiv;
        r = (int)ei[e];
        c = (int)ei[EE + e];
    } else {
        const int* ei = (const int*)eiv;
        r = ei[e];
        c = ei[EE + e];
    }
    if ((unsigned)r >= NN) r = 0;   // defensive clamp (should never trigger)
    if ((unsigned)c >= NN) c = 0;
    g_row[e] = r;
    g_col[e] = c;
    if (r != c) atomicAdd(&g_deg[r], 1);
}

__global__ void k_dinv() {
    int i = blockIdx.x * blockDim.x + threadIdx.x;
    if (i < NN) {
        int d = g_deg[i];
        g_dinv[i] = (d > 0) ? rsqrtf((float)d) : 0.f;
    }
}

// chunked exclusive scan of g_deg into g_indptr (chunk = 512)
__global__ void k_scan1() {
    __shared__ int s[512];
    int i = blockIdx.x * 512 + threadIdx.x;
    int v = (i < NN) ? g_deg[i] : 0;
    s[threadIdx.x] = v;
    __syncthreads();
    for (int off = 1; off < 512; off <<= 1) {
        int t = 0;
        if (threadIdx.x >= off) t = s[threadIdx.x - off];
        __syncthreads();
        if (threadIdx.x >= off) s[threadIdx.x] += t;
        __syncthreads();
    }
    if (i < NN) g_indptr[i] = s[threadIdx.x] - v;   // chunk-local exclusive
    if (threadIdx.x == 511) g_partials[blockIdx.x] = s[511];
}

__global__ void k_scan2(int nb) {
    __shared__ int s[512];
    int v = (threadIdx.x < nb) ? g_partials[threadIdx.x] : 0;
    s[threadIdx.x] = v;
    __syncthreads();
    for (int off = 1; off < 512; off <<= 1) {
        int t = 0;
        if (threadIdx.x >= off) t = s[threadIdx.x - off];
        __syncthreads();
        if (threadIdx.x >= off) s[threadIdx.x] += t;
        __syncthreads();
    }
    if (threadIdx.x < nb) g_partials[threadIdx.x] = s[threadIdx.x] - v;  // exclusive
    if (threadIdx.x == 511) g_indptr[NN] = s[511];                       // total
}

__global__ void k_scan3() {
    int i = blockIdx.x * blockDim.x + threadIdx.x;
    if (i < NN) {
        int p = g_indptr[i] + g_partials[i >> 9];
        g_indptr[i] = p;
        g_pos[i] = p;
    }
}

__global__ void k_fill() {
    int e = blockIdx.x * blockDim.x + threadIdx.x;
    if (e >= EE) return;
    int r = g_row[e];
    int c = g_col[e];
    if (r != c) {
        int p = atomicAdd(&g_pos[r], 1);
        g_ccsr[p] = c;
        g_wcsr[p] = -g_dinv[r] * g_dinv[c];
    }
}

// ---------------- layer 1 (F=3 padded to 4) ---------------------------------
__global__ void k_pad_x(const float* __restrict__ x) {
    int i = blockIdx.x * blockDim.x + threadIdx.x;
    if (i >= NN) return;
    float4* all = (float4*)g_tx1all;
    float4 t;
    t.x = x[3 * i + 0];
    t.y = x[3 * i + 1];
    t.z = x[3 * i + 2];
    t.w = 0.f;
    all[i] = t;
}

__global__ void k_l1_spmv(int ksrc, int kdst, int ktx0) {
    int i = blockIdx.x * blockDim.x + threadIdx.x;
    if (i >= NN) return;
    float4* all = (float4*)g_tx1all;
    const float4* v = all + (size_t)ksrc * NN;
    int s = g_indptr[i];
    int e = g_indptr[i + 1];
    float ax = 0.f, ay = 0.f, az = 0.f;
#pragma unroll 4
    for (int j = s; j < e; j++) {
        int   c  = g_ccsr[j];
        float wj = g_wcsr[j];
        float4 t = __ldg(&v[c]);
        ax = fmaf(wj, t.x, ax);
        ay = fmaf(wj, t.y, ay);
        az = fmaf(wj, t.z, az);
    }
    if (ktx0 >= 0) {
        float4 t0 = all[(size_t)ktx0 * NN + i];
        ax = 2.f * ax - t0.x;
        ay = 2.f * ay - t0.y;
        az = 2.f * az - t0.z;
    }
    float4 r; r.x = ax; r.y = ay; r.z = az; r.w = 0.f;
    all[(size_t)kdst * NN + i] = r;
}

// out[i][c] = silu( b1[c] + sum_{k,f} TxAll[k][i][f] * W1[k][f][c] )
__global__ void k_l1_gemm(const float* __restrict__ W1, const float* __restrict__ b1,
                          int outsel) {
    __shared__ float Ws[24 * 96];
    for (int t = threadIdx.x; t < 24 * 96; t += blockDim.x) Ws[t] = W1[t];
    __syncthreads();
    int gw   = (blockIdx.x * blockDim.x + threadIdx.x) >> 5;
    int lane = threadIdx.x & 31;
    if (gw >= NN) return;
    const float4* all = (const float4*)g_tx1all;
    float acc = b1[lane];
#pragma unroll
    for (int k = 0; k < 24; k++) {
        float4 t = all[(size_t)k * NN + gw];   // warp-uniform broadcast load
        acc = fmaf(t.x, Ws[k * 96 + 0  + lane], acc);
        acc = fmaf(t.y, Ws[k * 96 + 32 + lane], acc);
        acc = fmaf(t.z, Ws[k * 96 + 64 + lane], acc);
    }
    selbuf(outsel)[gw * 32 + lane] = silu(acc);
}

// ---------------- F=32 layers ------------------------------------------------
// out = b + h @ W0   (warp per node)
__global__ void k_init32(const float* __restrict__ W0, const float* __restrict__ b,
                         int hsel, int outsel) {
    __shared__ float Ws[1024];
    for (int t = threadIdx.x; t < 1024; t += blockDim.x) Ws[t] = W0[t];
    __syncthreads();
    int gw   = (blockIdx.x * blockDim.x + threadIdx.x) >> 5;
    int lane = threadIdx.x & 31;
    if (gw >= NN) return;
    float hv  = selbuf(hsel)[gw * 32 + lane];
    float acc = b[lane];
#pragma unroll
    for (int f = 0; f < 32; f++)
        acc = fmaf(__shfl_sync(FULLMASK, hv, f), Ws[f * 32 + lane], acc);
    selbuf(outsel)[gw * 32 + lane] = acc;
}

// Tx = L(v) (optionally 2L(v)-tx0); store Tx; out += Tx @ Wk; optional silu on out
__global__ void k_spmv32(const float* __restrict__ Wk,
                         int vsel, int tx0sel, int dstsel, int outsel, int dosilu) {
    __shared__ float Ws[1024];
    for (int t = threadIdx.x; t < 1024; t += blockDim.x) Ws[t] = Wk[t];
    __syncthreads();
    int gw   = (blockIdx.x * blockDim.x + threadIdx.x) >> 5;
    int lane = threadIdx.x & 31;
    if (gw >= NN) return;
    const float* v = selbuf(vsel);
    int s = g_indptr[gw];
    int e = g_indptr[gw + 1];
    float acc = 0.f;
    for (int base = s; base < e; base += 32) {
        int j = base + lane;
        int c = 0; float w = 0.f;
        if (j < e) { c = g_ccsr[j]; w = g_wcsr[j]; }
        int cnt = min(32, e - base);
        if (cnt == 32) {
#pragma unroll
            for (int q = 0; q < 32; q++) {
                int   cq = __shfl_sync(FULLMASK, c, q);
                float wq = __shfl_sync(FULLMASK, w, q);
                acc = fmaf(wq, __ldg(&v[cq * 32 + lane]), acc);
            }
        } else {
            for (int q = 0; q < cnt; q++) {
                int   cq = __shfl_sync(FULLMASK, c, q);
                float wq = __shfl_sync(FULLMASK, w, q);
                acc = fmaf(wq, __ldg(&v[cq * 32 + lane]), acc);
            }
        }
    }
    float tx = acc;
    if (tx0sel >= 0) tx = 2.f * acc - selbuf(tx0sel)[gw * 32 + lane];
    if (dstsel >= 0) selbuf(dstsel)[gw * 32 + lane] = tx;
    float o = selbuf(outsel)[gw * 32 + lane];
#pragma unroll
    for (int f = 0; f < 32; f++)
        o = fmaf(__shfl_sync(FULLMASK, tx, f), Ws[f * 32 + lane], o);
    if (dosilu) o = silu(o);
    selbuf(outsel)[gw * 32 + lane] = o;
}

// layer 4: K=1, no bias: d_out[i] = sum_f h[i][f] * W4[f]
__global__ void k_final(const float* __restrict__ W4, int hsel, float* __restrict__ dout) {
    int gw   = (blockIdx.x * blockDim.x + threadIdx.x) >> 5;
    int lane = threadIdx.x & 31;
    if (gw >= NN) return;
    float p = selbuf(hsel)[gw * 32 + lane] * W4[lane];
#pragma unroll
    for (int off = 16; off; off >>= 1) p += __shfl_xor_sync(FULLMASK, p, off);
    if (lane == 0) dout[gw] = p;
}

// ---------------- host orchestration ----------------------------------------
static void layer32(const float* W, const float* b, int hsel, int outsel,
                    int s1, int s2, int K, int blocksWarp) {
    k_init32<<<blocksWarp, 256>>>(W, b, hsel, outsel);
    // k = 1
    k_spmv32<<<blocksWarp, 256>>>(W + 1024, hsel, -1, s1, outsel, (K == 2) ? 1 : 0);
    int p0 = hsel, p1 = s1, f = s2;
    for (int k = 2; k < K; k++) {
        k_spmv32<<<blocksWarp, 256>>>(W + (size_t)k * 1024, p1, p0, f, outsel,
                                      (k == K - 1) ? 1 : 0);
        int np0 = p1, np1 = f, nf = p0;
        p0 = np0; p1 = np1; f = nf;
    }
}

extern "C" void kernel_launch(void* const* d_in, const int* in_sizes, int n_in,
                              void* d_out, int out_size) {
    const float* x  = (const float*)d_in[0];
    const void*  ei = d_in[1];
    // d_in[2] batch, d_in[3] edge_attr: unused by the network
    const float* W1 = (const float*)d_in[4];
    const float* b1 = (const float*)d_in[5];
    const float* W2 = (const float*)d_in[6];
    const float* b2 = (const float*)d_in[7];
    const float* W3 = (const float*)d_in[8];
    const float* b3 = (const float*)d_in[9];
    const float* W4 = (const float*)d_in[10];
    float* out = (float*)d_out;

    const int blocksN    = (NN + 255) / 256;          // thread-per-node
    const int blocksE    = (EE + 255) / 256;          // thread-per-edge
    const int blocksScan = (NN + 511) / 512;          // 196
    const int blocksWarp = (NN * 32 + 255) / 256;     // warp-per-node (12500)

    // --- dtype probe + CSR build ---
    k_detect<<<1, 32>>>((const int*)ei);
    k_zero_deg<<<blocksN, 256>>>();
    k_edges<<<blocksE, 256>>>(ei);
    k_dinv<<<blocksN, 256>>>();
    k_scan1<<<blocksScan, 512>>>();
    k_scan2<<<1, 512>>>(blocksScan);
    k_scan3<<<blocksN, 256>>>();
    k_fill<<<blocksE, 256>>>();

    // --- layer 1: K=24, 3 -> 32, silu ---
    k_pad_x<<<blocksN, 256>>>(x);
    k_l1_spmv<<<blocksN, 256>>>(0, 1, -1);
    for (int k = 2; k < 24; k++)
        k_l1_spmv<<<blocksN, 256>>>(k - 1, k, k - 2);
    k_l1_gemm<<<blocksWarp, 256>>>(W1, b1, /*outsel=*/0);   // h1 -> bufA

    // --- layer 2: K=12, 32 -> 32, silu.  h=A(0), out=B(1), scratch C(2),D(3) ---
    layer32(W2, b2, 0, 1, 2, 3, 12, blocksWarp);            // h2 -> bufB

    // --- layer 3: K=10, 32 -> 32, silu.  h=B(1), out=A(0), scratch C(2),D(3) ---
    layer32(W3, b3, 1, 0, 2, 3, 10, blocksWarp);            // h3 -> bufA

    // --- layer 4: K=1, 32 -> 1, no bias ---
    k_final<<<blocksWarp, 256>>>(W4, 0, out);

    (void)in_sizes; (void)n_in; (void)out_size;
}

// round 3
// speedup vs baseline: 1.0008x; 1.0008x over previous
#include <cuda_runtime.h>
#include <cstdint>

#define NN 100000
#define EE 3200000
#define FC 32
#define FULLMASK 0xFFFFFFFFu

// ---------------- scratch (device globals; no allocation anywhere) ----------
__device__ int   g_is64;
__device__ int   g_row[EE];
__device__ int   g_col[EE];
__device__ int   g_deg[NN];
__device__ float g_dinv[NN];
__device__ int   g_indptr[NN + 1];
__device__ int   g_pos[NN];
__device__ int2  g_ecsr[EE];          // packed {col, float_bits(weight)}
__device__ int   g_partials[512];

__device__ float g_tx1all[24 * NN * 4];   // layer1 Chebyshev basis, float4-padded
__device__ float g_bufA[NN * FC];
__device__ float g_bufB[NN * FC];
__device__ float g_bufC[NN * FC];
__device__ float g_bufD[NN * FC];

__device__ __forceinline__ float* selbuf(int s) {
    switch (s) {
        case 0:  return g_bufA;
        case 1:  return g_bufB;
        case 2:  return g_bufC;
        default: return g_bufD;
    }
}

__device__ __forceinline__ float silu(float x) {
    return x / (1.f + __expf(-x));
}

// ---------------- dtype detection (parallel, 1 memory round-trip) -----------
// int64 edge_index with values < 2^31 -> every odd int32 word is 0.
__global__ void k_detect(const int* __restrict__ ei32) {
    __shared__ int ok;
    if (threadIdx.x == 0) ok = 1;
    __syncthreads();
    if (ei32[2 * threadIdx.x + 1] != 0) ok = 0;
    __syncthreads();
    if (threadIdx.x == 0) g_is64 = ok;
}

// ---------------- graph preprocessing ---------------------------------------
__global__ void k_zero_deg() {
    int i = blockIdx.x * blockDim.x + threadIdx.x;
    if (i < NN) g_deg[i] = 0;
}

__global__ void k_edges(const void* __restrict__ eiv) {
    int e = blockIdx.x * blockDim.x + threadIdx.x;
    if (e >= EE) return;
    int r, c;
    if (g_is64) {
        const long long* ei = (const long long*)eiv;
        r = (int)ei[e];
        c = (int)ei[EE + e];
    } else {
        const int* ei = (const int*)eiv;
        r = ei[e];
        c = ei[EE + e];
    }
    if ((unsigned)r >= NN) r = 0;   // defensive clamp (should never trigger)
    if ((unsigned)c >= NN) c = 0;
    g_row[e] = r;
    g_col[e] = c;
    if (r != c) atomicAdd(&g_deg[r], 1);
}

__global__ void k_dinv() {
    int i = blockIdx.x * blockDim.x + threadIdx.x;
    if (i < NN) {
        int d = g_deg[i];
        g_dinv[i] = (d > 0) ? rsqrtf((float)d) : 0.f;
    }
}

// chunked exclusive scan of g_deg into g_indptr (chunk = 512)
__global__ void k_scan1() {
    __shared__ int s[512];
    int i = blockIdx.x * 512 + threadIdx.x;
    int v = (i < NN) ? g_deg[i] : 0;
    s[threadIdx.x] = v;
    __syncthreads();
    for (int off = 1; off < 512; off <<= 1) {
        int t = 0;
        if (threadIdx.x >= off) t = s[threadIdx.x - off];
        __syncthreads();
        if (threadIdx.x >= off) s[threadIdx.x] += t;
        __syncthreads();
    }
    if (i < NN) g_indptr[i] = s[threadIdx.x] - v;   // chunk-local exclusive
    if (threadIdx.x == 511) g_partials[blockIdx.x] = s[511];
}

__global__ void k_scan2(int nb) {
    __shared__ int s[512];
    int v = (threadIdx.x < nb) ? g_partials[threadIdx.x] : 0;
    s[threadIdx.x] = v;
    __syncthreads();
    for (int off = 1; off < 512; off <<= 1) {
        int t = 0;
        if (threadIdx.x >= off) t = s[threadIdx.x - off];
        __syncthreads();
        if (threadIdx.x >= off) s[threadIdx.x] += t;
        __syncthreads();
    }
    if (threadIdx.x < nb) g_partials[threadIdx.x] = s[threadIdx.x] - v;  // exclusive
    if (threadIdx.x == 511) g_indptr[NN] = s[511];                       // total
}

__global__ void k_scan3() {
    int i = blockIdx.x * blockDim.x + threadIdx.x;
    if (i < NN) {
        int p = g_indptr[i] + g_partials[i >> 9];
        g_indptr[i] = p;
        g_pos[i] = p;
    }
}

__global__ void k_fill() {
    int e = blockIdx.x * blockDim.x + threadIdx.x;
    if (e >= EE) return;
    int r = g_row[e];
    int c = g_col[e];
    if (r != c) {
        int p = atomicAdd(&g_pos[r], 1);
        int2 pk;
        pk.x = c;
        pk.y = __float_as_int(-g_dinv[r] * g_dinv[c]);
        g_ecsr[p] = pk;
    }
}

// ---------------- layer 1 (F=3 padded to 4), warp per node ------------------
__global__ void k_pad_x(const float* __restrict__ x) {
    int i = blockIdx.x * blockDim.x + threadIdx.x;
    if (i >= NN) return;
    float4* all = (float4*)g_tx1all;
    float4 t;
    t.x = x[3 * i + 0];
    t.y = x[3 * i + 1];
    t.z = x[3 * i + 2];
    t.w = 0.f;
    all[i] = t;
}

__global__ void k_l1_spmv(int ksrc, int kdst, int ktx0) {
    int gw   = (blockIdx.x * blockDim.x + threadIdx.x) >> 5;
    int lane = threadIdx.x & 31;
    if (gw >= NN) return;
    float4* all = (float4*)g_tx1all;
    const float4* v = all + (size_t)ksrc * NN;
    int s = g_indptr[gw];
    int e = g_indptr[gw + 1];
    float ax = 0.f, ay = 0.f, az = 0.f;
    for (int base = s; base < e; base += 32) {
        int j = base + lane;
        int c = 0; float w = 0.f;
        if (j < e) {
            int2 p = g_ecsr[j];
            c = p.x;
            w = __int_as_float(p.y);
        }
        float4 t = __ldg(&v[c]);
        ax = fmaf(w, t.x, ax);
        ay = fmaf(w, t.y, ay);
        az = fmaf(w, t.z, az);
    }
#pragma unroll
    for (int off = 16; off; off >>= 1) {
        ax += __shfl_xor_sync(FULLMASK, ax, off);
        ay += __shfl_xor_sync(FULLMASK, ay, off);
        az += __shfl_xor_sync(FULLMASK, az, off);
    }
    if (lane == 0) {
        if (ktx0 >= 0) {
            float4 t0 = all[(size_t)ktx0 * NN + gw];
            ax = 2.f * ax - t0.x;
            ay = 2.f * ay - t0.y;
            az = 2.f * az - t0.z;
        }
        float4 r; r.x = ax; r.y = ay; r.z = az; r.w = 0.f;
        all[(size_t)kdst * NN + gw] = r;
    }
}

// out[i][c] = silu( b1[c] + sum_{k,f} TxAll[k][i][f] * W1[k][f][c] )
__global__ void k_l1_gemm(const float* __restrict__ W1, const float* __restrict__ b1,
                          int outsel) {
    __shared__ float Ws[24 * 96];
    for (int t = threadIdx.x; t < 24 * 96; t += blockDim.x) Ws[t] = W1[t];
    __syncthreads();
    int gw   = (blockIdx.x * blockDim.x + threadIdx.x) >> 5;
    int lane = threadIdx.x & 31;
    if (gw >= NN) return;
    const float4* all = (const float4*)g_tx1all;
    float acc = b1[lane];
#pragma unroll
    for (int k = 0; k < 24; k++) {
        float4 t = all[(size_t)k * NN + gw];   // warp-uniform broadcast load
        acc = fmaf(t.x, Ws[k * 96 + 0  + lane], acc);
        acc = fmaf(t.y, Ws[k * 96 + 32 + lane], acc);
        acc = fmaf(t.z, Ws[k * 96 + 64 + lane], acc);
    }
    selbuf(outsel)[gw * 32 + lane] = silu(acc);
}

// ---------------- F=32 layers ------------------------------------------------
// shared gather core: acc[lane] = sum_j w_j * v[c_j*32 + lane]
__device__ __forceinline__ float gather32(const float* __restrict__ v,
                                          int s, int e, int lane) {
    float acc = 0.f;
    for (int base = s; base < e; base += 32) {
        int j = base + lane;
        int c = 0; float w = 0.f;
        if (j < e) {
            int2 p = g_ecsr[j];
            c = p.x;
            w = __int_as_float(p.y);
        }
        int cnt = min(32, e - base);
        if (cnt == 32) {
#pragma unroll
            for (int q = 0; q < 32; q++) {
                int   cq = __shfl_sync(FULLMASK, c, q);
                float wq = __shfl_sync(FULLMASK, w, q);
                acc = fmaf(wq, __ldg(&v[cq * 32 + lane]), acc);
            }
        } else {
            for (int q = 0; q < cnt; q++) {
                int   cq = __shfl_sync(FULLMASK, c, q);
                float wq = __shfl_sync(FULLMASK, w, q);
                acc = fmaf(wq, __ldg(&v[cq * 32 + lane]), acc);
            }
        }
    }
    return acc;
}

// first step of a layer: o = b + h@W0 + Tx1@W1, Tx1 = L(h) stored to dst
__global__ void k_spmv32_first(const float* __restrict__ W, const float* __restrict__ b,
                               int hsel, int dstsel, int outsel) {
    __shared__ float Ws0[1024];
    __shared__ float Ws1[1024];
    for (int t = threadIdx.x; t < 1024; t += blockDim.x) {
        Ws0[t] = W[t];
        Ws1[t] = W[1024 + t];
    }
    __syncthreads();
    int gw   = (blockIdx.x * blockDim.x + threadIdx.x) >> 5;
    int lane = threadIdx.x & 31;
    if (gw >= NN) return;
    const float* h = selbuf(hsel);
    float hv = h[gw * 32 + lane];
    float o  = b[lane];
#pragma unroll
    for (int f = 0; f < 32; f++)
        o = fmaf(__shfl_sync(FULLMASK, hv, f), Ws0[f * 32 + lane], o);
    float tx = gather32(h, g_indptr[gw], g_indptr[gw + 1], lane);
    selbuf(dstsel)[gw * 32 + lane] = tx;
#pragma unroll
    for (int f = 0; f < 32; f++)
        o = fmaf(__shfl_sync(FULLMASK, tx, f), Ws1[f * 32 + lane], o);
    selbuf(outsel)[gw * 32 + lane] = o;
}

// general step k>=2: tx = 2 L(v) - tx0; optionally store tx; o += tx@Wk; opt silu
__global__ void k_spmv32(const float* __restrict__ Wk,
                         int vsel, int tx0sel, int dstsel, int outsel, int dosilu) {
    __shared__ float Ws[1024];
    for (int t = threadIdx.x; t < 1024; t += blockDim.x) Ws[t] = Wk[t];
    __syncthreads();
    int gw   = (blockIdx.x * blockDim.x + threadIdx.x) >> 5;
    int lane = threadIdx.x & 31;
    if (gw >= NN) return;
    const float* v = selbuf(vsel);
    float acc = gather32(v, g_indptr[gw], g_indptr[gw + 1], lane);
    float tx  = 2.f * acc - selbuf(tx0sel)[gw * 32 + lane];
    if (dstsel >= 0) selbuf(dstsel)[gw * 32 + lane] = tx;
    float o = selbuf(outsel)[gw * 32 + lane];
#pragma unroll
    for (int f = 0; f < 32; f++)
        o = fmaf(__shfl_sync(FULLMASK, tx, f), Ws[f * 32 + lane], o);
    if (dosilu) o = silu(o);
    selbuf(outsel)[gw * 32 + lane] = o;
}

// layer 4: K=1, no bias: d_out[i] = sum_f h[i][f] * W4[f]
__global__ void k_final(const float* __restrict__ W4, int hsel, float* __restrict__ dout) {
    int gw   = (blockIdx.x * blockDim.x + threadIdx.x) >> 5;
    int lane = threadIdx.x & 31;
    if (gw >= NN) return;
    float p = selbuf(hsel)[gw * 32 + lane] * W4[lane];
#pragma unroll
    for (int off = 16; off; off >>= 1) p += __shfl_xor_sync(FULLMASK, p, off);
    if (lane == 0) dout[gw] = p;
}

// ---------------- host orchestration ----------------------------------------
static void layer32(const float* W, const float* b, int hsel, int outsel,
                    int s1, int s2, int K, int blocksWarp) {
    // k=0 (identity) + k=1 fused
    k_spmv32_first<<<blocksWarp, 256>>>(W, b, hsel, s1, outsel);
    int p0 = hsel, p1 = s1, f = s2;
    for (int k = 2; k < K; k++) {
        int last = (k == K - 1);
        k_spmv32<<<blocksWarp, 256>>>(W + (size_t)k * 1024, p1, p0,
                                      last ? -1 : f, outsel, last);
        int np0 = p1, np1 = f, nf = p0;
        p0 = np0; p1 = np1; f = nf;
    }
}

extern "C" void kernel_launch(void* const* d_in, const int* in_sizes, int n_in,
                              void* d_out, int out_size) {
    const float* x  = (const float*)d_in[0];
    const void*  ei = d_in[1];
    // d_in[2] batch, d_in[3] edge_attr: unused by the network
    const float* W1 = (const float*)d_in[4];
    const float* b1 = (const float*)d_in[5];
    const float* W2 = (const float*)d_in[6];
    const float* b2 = (const float*)d_in[7];
    const float* W3 = (const float*)d_in[8];
    const float* b3 = (const float*)d_in[9];
    const float* W4 = (const float*)d_in[10];
    float* out = (float*)d_out;

    const int blocksN    = (NN + 255) / 256;          // thread-per-node
    const int blocksE    = (EE + 255) / 256;          // thread-per-edge
    const int blocksScan = (NN + 511) / 512;          // 196
    const int blocksWarp = (NN * 32 + 255) / 256;     // warp-per-node (12500)

    // --- dtype probe + CSR build ---
    k_detect<<<1, 512>>>((const int*)ei);
    k_zero_deg<<<blocksN, 256>>>();
    k_edges<<<blocksE, 256>>>(ei);
    k_dinv<<<blocksN, 256>>>();
    k_scan1<<<blocksScan, 512>>>();
    k_scan2<<<1, 512>>>(blocksScan);
    k_scan3<<<blocksN, 256>>>();
    k_fill<<<blocksE, 256>>>();

    // --- layer 1: K=24, 3 -> 32, silu (warp-per-node spmvs) ---
    k_pad_x<<<blocksN, 256>>>(x);
    k_l1_spmv<<<blocksWarp, 256>>>(0, 1, -1);
    for (int k = 2; k < 24; k++)
        k_l1_spmv<<<blocksWarp, 256>>>(k - 1, k, k - 2);
    k_l1_gemm<<<blocksWarp, 256>>>(W1, b1, /*outsel=*/0);   // h1 -> bufA

    // --- layer 2: K=12, 32 -> 32, silu.  h=A(0), out=B(1), scratch C(2),D(3) ---
    layer32(W2, b2, 0, 1, 2, 3, 12, blocksWarp);            // h2 -> bufB

    // --- layer 3: K=10, 32 -> 32, silu.  h=B(1), out=A(0), scratch C(2),D(3) ---
    layer32(W3, b3, 1, 0, 2, 3, 10, blocksWarp);            // h3 -> bufA

    // --- layer 4: K=1, 32 -> 1, no bias ---
    k_final<<<blocksWarp, 256>>>(W4, 0, out);

    (void)in_sizes; (void)n_in; (void)out_size;
}

// round 4
// speedup vs baseline: 1.0260x; 1.0252x over previous
#include <cuda_runtime.h>
#include <cuda_fp16.h>
#include <cstdint>

#define NN 100000
#define EE 3200000
#define FC 32
#define FULLMASK 0xFFFFFFFFu

// ---------------- scratch (device globals; no allocation anywhere) ----------
__device__ int   g_is64;
__device__ int   g_row[EE];
__device__ int   g_col[EE];
__device__ int   g_deg[NN];
__device__ float g_dinv[NN];
__device__ int   g_indptr[NN + 1];
__device__ int   g_pos[NN];
__device__ int2  g_ecsr[EE];          // packed {col, float_bits(weight)}
__device__ int   g_partials[512];

__device__ float g_tx1all[24 * NN * 4];   // layer1 Chebyshev basis, float4-padded
__device__ float  g_bufA[NN * FC];
__device__ float  g_bufB[NN * FC];
__device__ float  g_bufC[NN * FC];
__device__ float  g_bufD[NN * FC];
__device__ __half g_h16A[NN * FC];        // fp16 mirrors (gather operands)
__device__ __half g_h16B[NN * FC];
__device__ __half g_h16C[NN * FC];
__device__ __half g_h16D[NN * FC];

__device__ __forceinline__ float* selbuf(int s) {
    switch (s) {
        case 0:  return g_bufA;
        case 1:  return g_bufB;
        case 2:  return g_bufC;
        default: return g_bufD;
    }
}
__device__ __forceinline__ __half* sel16(int s) {
    switch (s) {
        case 0:  return g_h16A;
        case 1:  return g_h16B;
        case 2:  return g_h16C;
        default: return g_h16D;
    }
}

__device__ __forceinline__ float silu(float x) {
    return x / (1.f + __expf(-x));
}

// ---------------- dtype detection (parallel, 1 memory round-trip) -----------
__global__ void k_detect(const int* __restrict__ ei32) {
    __shared__ int ok;
    if (threadIdx.x == 0) ok = 1;
    __syncthreads();
    if (ei32[2 * threadIdx.x + 1] != 0) ok = 0;
    __syncthreads();
    if (threadIdx.x == 0) g_is64 = ok;
}

// ---------------- graph preprocessing ---------------------------------------
__global__ void k_zero_deg() {
    int i = blockIdx.x * blockDim.x + threadIdx.x;
    if (i < NN) g_deg[i] = 0;
}

__global__ void k_edges(const void* __restrict__ eiv) {
    int e = blockIdx.x * blockDim.x + threadIdx.x;
    if (e >= EE) return;
    int r, c;
    if (g_is64) {
        const long long* ei = (const long long*)eiv;
        r = (int)ei[e];
        c = (int)ei[EE + e];
    } else {
        const int* ei = (const int*)eiv;
        r = ei[e];
        c = ei[EE + e];
    }
    if ((unsigned)r >= NN) r = 0;
    if ((unsigned)c >= NN) c = 0;
    g_row[e] = r;
    g_col[e] = c;
    if (r != c) atomicAdd(&g_deg[r], 1);
}

__global__ void k_dinv() {
    int i = blockIdx.x * blockDim.x + threadIdx.x;
    if (i < NN) {
        int d = g_deg[i];
        g_dinv[i] = (d > 0) ? rsqrtf((float)d) : 0.f;
    }
}

// chunked exclusive scan of g_deg into g_indptr (chunk = 512)
__global__ void k_scan1() {
    __shared__ int s[512];
    int i = blockIdx.x * 512 + threadIdx.x;
    int v = (i < NN) ? g_deg[i] : 0;
    s[threadIdx.x] = v;
    __syncthreads();
    for (int off = 1; off < 512; off <<= 1) {
        int t = 0;
        if (threadIdx.x >= off) t = s[threadIdx.x - off];
        __syncthreads();
        if (threadIdx.x >= off) s[threadIdx.x] += t;
        __syncthreads();
    }
    if (i < NN) g_indptr[i] = s[threadIdx.x] - v;
    if (threadIdx.x == 511) g_partials[blockIdx.x] = s[511];
}

__global__ void k_scan2(int nb) {
    __shared__ int s[512];
    int v = (threadIdx.x < nb) ? g_partials[threadIdx.x] : 0;
    s[threadIdx.x] = v;
    __syncthreads();
    for (int off = 1; off < 512; off <<= 1) {
        int t = 0;
        if (threadIdx.x >= off) t = s[threadIdx.x - off];
        __syncthreads();
        if (threadIdx.x >= off) s[threadIdx.x] += t;
        __syncthreads();
    }
    if (threadIdx.x < nb) g_partials[threadIdx.x] = s[threadIdx.x] - v;
    if (threadIdx.x == 511) g_indptr[NN] = s[511];
}

__global__ void k_scan3() {
    int i = blockIdx.x * blockDim.x + threadIdx.x;
    if (i < NN) {
        int p = g_indptr[i] + g_partials[i >> 9];
        g_indptr[i] = p;
        g_pos[i] = p;
    }
}

__global__ void k_fill() {
    int e = blockIdx.x * blockDim.x + threadIdx.x;
    if (e >= EE) return;
    int r = g_row[e];
    int c = g_col[e];
    if (r != c) {
        int p = atomicAdd(&g_pos[r], 1);
        int2 pk;
        pk.x = c;
        pk.y = __float_as_int(-g_dinv[r] * g_dinv[c]);
        g_ecsr[p] = pk;
    }
}

// ---------------- layer 1 (F=3 padded to 4), warp per node ------------------
__global__ void k_pad_x(const float* __restrict__ x) {
    int i = blockIdx.x * blockDim.x + threadIdx.x;
    if (i >= NN) return;
    float4* all = (float4*)g_tx1all;
    float4 t;
    t.x = x[3 * i + 0];
    t.y = x[3 * i + 1];
    t.z = x[3 * i + 2];
    t.w = 0.f;
    all[i] = t;
}

__global__ void k_l1_spmv(int ksrc, int kdst, int ktx0) {
    int gw   = (blockIdx.x * blockDim.x + threadIdx.x) >> 5;
    int lane = threadIdx.x & 31;
    if (gw >= NN) return;
    float4* all = (float4*)g_tx1all;
    const float4* v = all + (size_t)ksrc * NN;
    int s = g_indptr[gw];
    int e = g_indptr[gw + 1];
    float ax = 0.f, ay = 0.f, az = 0.f;
    for (int base = s; base < e; base += 32) {
        int j = base + lane;
        int c = 0; float w = 0.f;
        if (j < e) {
            int2 p = __ldg(&g_ecsr[j]);
            c = p.x;
            w = __int_as_float(p.y);
        }
        float4 t = __ldg(&v[c]);
        ax = fmaf(w, t.x, ax);
        ay = fmaf(w, t.y, ay);
        az = fmaf(w, t.z, az);
    }
#pragma unroll
    for (int off = 16; off; off >>= 1) {
        ax += __shfl_xor_sync(FULLMASK, ax, off);
        ay += __shfl_xor_sync(FULLMASK, ay, off);
        az += __shfl_xor_sync(FULLMASK, az, off);
    }
    if (lane == 0) {
        if (ktx0 >= 0) {
            float4 t0 = all[(size_t)ktx0 * NN + gw];
            ax = 2.f * ax - t0.x;
            ay = 2.f * ay - t0.y;
            az = 2.f * az - t0.z;
        }
        float4 r; r.x = ax; r.y = ay; r.z = az; r.w = 0.f;
        all[(size_t)kdst * NN + gw] = r;
    }
}

// out[i][c] = silu( b1[c] + sum_{k,f} TxAll[k][i][f] * W1[k][f][c] )
__global__ void k_l1_gemm(const float* __restrict__ W1, const float* __restrict__ b1,
                          int outsel) {
    __shared__ float Ws[24 * 96];
    for (int t = threadIdx.x; t < 24 * 96; t += blockDim.x) Ws[t] = W1[t];
    __syncthreads();
    int gw   = (blockIdx.x * blockDim.x + threadIdx.x) >> 5;
    int lane = threadIdx.x & 31;
    if (gw >= NN) return;
    const float4* all = (const float4*)g_tx1all;
    float acc = b1[lane];
#pragma unroll
    for (int k = 0; k < 24; k++) {
        float4 t = all[(size_t)k * NN + gw];
        acc = fmaf(t.x, Ws[k * 96 + 0  + lane], acc);
        acc = fmaf(t.y, Ws[k * 96 + 32 + lane], acc);
        acc = fmaf(t.z, Ws[k * 96 + 64 + lane], acc);
    }
    float r = silu(acc);
    selbuf(outsel)[gw * 32 + lane] = r;
    sel16(outsel)[gw * 32 + lane] = __float2half(r);
}

// ---------------- F=32 layers ------------------------------------------------
// gather core: acc[lane] = sum_j w_j * v16[c_j*32 + lane]
// edge (c,w) pairs are warp-uniform broadcast loads (L1-resident stream);
// the feature gather is a 64B fp16 row per edge.
__device__ __forceinline__ float gather16(const __half* __restrict__ v,
                                          int s, int e, int lane) {
    float acc = 0.f;
#pragma unroll 4
    for (int j = s; j < e; j++) {
        int2 p = __ldg(&g_ecsr[j]);
        float w = __int_as_float(p.y);
        acc = fmaf(w, __half2float(__ldg(&v[p.x * 32 + lane])), acc);
    }
    return acc;
}

// first step of a layer: o = b + h@W0 + Tx1@W1, Tx1 = L(h) stored to dst(+fp16)
__global__ void k_spmv32_first(const float* __restrict__ W, const float* __restrict__ b,
                               int hsel, int dstsel, int outsel) {
    __shared__ float Ws0[1024];
    __shared__ float Ws1[1024];
    for (int t = threadIdx.x; t < 1024; t += blockDim.x) {
        Ws0[t] = W[t];
        Ws1[t] = W[1024 + t];
    }
    __syncthreads();
    int gw   = (blockIdx.x * blockDim.x + threadIdx.x) >> 5;
    int lane = threadIdx.x & 31;
    if (gw >= NN) return;
    float hv = selbuf(hsel)[gw * 32 + lane];
    float o  = b[lane];
#pragma unroll
    for (int f = 0; f < 32; f++)
        o = fmaf(__shfl_sync(FULLMASK, hv, f), Ws0[f * 32 + lane], o);
    float tx = gather16(sel16(hsel), g_indptr[gw], g_indptr[gw + 1], lane);
    selbuf(dstsel)[gw * 32 + lane] = tx;
    sel16(dstsel)[gw * 32 + lane] = __float2half(tx);
#pragma unroll
    for (int f = 0; f < 32; f++)
        o = fmaf(__shfl_sync(FULLMASK, tx, f), Ws1[f * 32 + lane], o);
    selbuf(outsel)[gw * 32 + lane] = o;
}

// step k>=2: tx = 2 L(v) - tx0; opt store tx(+fp16); o += tx@Wk; opt silu(+fp16)
__global__ void k_spmv32(const float* __restrict__ Wk,
                         int vsel, int tx0sel, int dstsel, int outsel, int dosilu) {
    __shared__ float Ws[1024];
    for (int t = threadIdx.x; t < 1024; t += blockDim.x) Ws[t] = Wk[t];
    __syncthreads();
    int gw   = (blockIdx.x * blockDim.x + threadIdx.x) >> 5;
    int lane = threadIdx.x & 31;
    if (gw >= NN) return;
    float acc = gather16(sel16(vsel), g_indptr[gw], g_indptr[gw + 1], lane);
    float tx  = 2.f * acc - selbuf(tx0sel)[gw * 32 + lane];
    if (dstsel >= 0) {
        selbuf(dstsel)[gw * 32 + lane] = tx;
        sel16(dstsel)[gw * 32 + lane] = __float2half(tx);
    }
    float o = selbuf(outsel)[gw * 32 + lane];
#pragma unroll
    for (int f = 0; f < 32; f++)
        o = fmaf(__shfl_sync(FULLMASK, tx, f), Ws[f * 32 + lane], o);
    if (dosilu) {
        o = silu(o);
        sel16(outsel)[gw * 32 + lane] = __float2half(o);   // next layer's gather input
    }
    selbuf(outsel)[gw * 32 + lane] = o;
}

// layer 4: K=1, no bias: d_out[i] = sum_f h[i][f] * W4[f]
__global__ void k_final(const float* __restrict__ W4, int hsel, float* __restrict__ dout) {
    int gw   = (blockIdx.x * blockDim.x + threadIdx.x) >> 5;
    int lane = threadIdx.x & 31;
    if (gw >= NN) return;
    float p = selbuf(hsel)[gw * 32 + lane] * W4[lane];
#pragma unroll
    for (int off = 16; off; off >>= 1) p += __shfl_xor_sync(FULLMASK, p, off);
    if (lane == 0) dout[gw] = p;
}

// ---------------- host orchestration ----------------------------------------
static void layer32(const float* W, const float* b, int hsel, int outsel,
                    int s1, int s2, int K, int blocksWarp) {
    k_spmv32_first<<<blocksWarp, 256>>>(W, b, hsel, s1, outsel);
    int p0 = hsel, p1 = s1, f = s2;
    for (int k = 2; k < K; k++) {
        int last = (k == K - 1);
        k_spmv32<<<blocksWarp, 256>>>(W + (size_t)k * 1024, p1, p0,
                                      last ? -1 : f, outsel, last);
        int np0 = p1, np1 = f, nf = p0;
        p0 = np0; p1 = np1; f = nf;
    }
}

extern "C" void kernel_launch(void* const* d_in, const int* in_sizes, int n_in,
                              void* d_out, int out_size) {
    const float* x  = (const float*)d_in[0];
    const void*  ei = d_in[1];
    const float* W1 = (const float*)d_in[4];
    const float* b1 = (const float*)d_in[5];
    const float* W2 = (const float*)d_in[6];
    const float* b2 = (const float*)d_in[7];
    const float* W3 = (const float*)d_in[8];
    const float* b3 = (const float*)d_in[9];
    const float* W4 = (const float*)d_in[10];
    float* out = (float*)d_out;

    const int blocksN    = (NN + 255) / 256;
    const int blocksE    = (EE + 255) / 256;
    const int blocksScan = (NN + 511) / 512;
    const int blocksWarp = (NN * 32 + 255) / 256;

    // --- dtype probe + CSR build ---
    k_detect<<<1, 512>>>((const int*)ei);
    k_zero_deg<<<blocksN, 256>>>();
    k_edges<<<blocksE, 256>>>(ei);
    k_dinv<<<blocksN, 256>>>();
    k_scan1<<<blocksScan, 512>>>();
    k_scan2<<<1, 512>>>(blocksScan);
    k_scan3<<<blocksN, 256>>>();
    k_fill<<<blocksE, 256>>>();

    // --- layer 1: K=24, 3 -> 32, silu ---
    k_pad_x<<<blocksN, 256>>>(x);
    k_l1_spmv<<<blocksWarp, 256>>>(0, 1, -1);
    for (int k = 2; k < 24; k++)
        k_l1_spmv<<<blocksWarp, 256>>>(k - 1, k, k - 2);
    k_l1_gemm<<<blocksWarp, 256>>>(W1, b1, /*outsel=*/0);   // h1 -> bufA (+fp16)

    // --- layer 2: K=12 ---
    layer32(W2, b2, 0, 1, 2, 3, 12, blocksWarp);            // h2 -> bufB (+fp16)

    // --- layer 3: K=10 ---
    layer32(W3, b3, 1, 0, 2, 3, 10, blocksWarp);            // h3 -> bufA (+fp16)

    // --- layer 4: K=1, 32 -> 1, no bias ---
    k_final<<<blocksWarp, 256>>>(W4, 0, out);

    (void)in_sizes; (void)n_in; (void)out_size;
}

// round 5
// speedup vs baseline: 1.2124x; 1.1817x over previous
#include <cuda_runtime.h>
#include <cuda_fp16.h>
#include <cstdint>

#define NN 100000
#define EE 3200000
#define FC 32
#define FULLMASK 0xFFFFFFFFu

// ---------------- scratch (device globals; no allocation anywhere) ----------
__device__ int   g_is64;
__device__ int   g_row[EE];
__device__ int   g_col[EE];
__device__ int   g_deg[NN];
__device__ float g_dinv[NN];
__device__ int   g_indptr[NN + 1];
__device__ int   g_pos[NN];
__device__ int2  g_ecsr[EE];          // packed {col, float_bits(weight)}
__device__ int   g_partials[512];

__device__ float g_tx1all[24 * NN * 4];   // layer1 basis fp32, float4-padded
__device__ uint2 g_tx1h[24 * NN];         // layer1 basis fp16x4 mirror (gather operand)
__device__ float  g_bufA[NN * FC];
__device__ float  g_bufB[NN * FC];
__device__ float  g_bufC[NN * FC];
__device__ float  g_bufD[NN * FC];
__device__ __half g_h16A[NN * FC];        // fp16 mirrors (gather operands)
__device__ __half g_h16B[NN * FC];
__device__ __half g_h16C[NN * FC];
__device__ __half g_h16D[NN * FC];

__device__ __forceinline__ float* selbuf(int s) {
    switch (s) {
        case 0:  return g_bufA;
        case 1:  return g_bufB;
        case 2:  return g_bufC;
        default: return g_bufD;
    }
}
__device__ __forceinline__ __half* sel16(int s) {
    switch (s) {
        case 0:  return g_h16A;
        case 1:  return g_h16B;
        case 2:  return g_h16C;
        default: return g_h16D;
    }
}

__device__ __forceinline__ float silu(float x) {
    return x / (1.f + __expf(-x));
}

__device__ __forceinline__ uint2 pack4h(float a, float b, float c, float d) {
    __half2 lo = __floats2half2_rn(a, b);
    __half2 hi = __floats2half2_rn(c, d);
    uint2 r;
    r.x = *reinterpret_cast<unsigned*>(&lo);
    r.y = *reinterpret_cast<unsigned*>(&hi);
    return r;
}

// ---------------- dtype detection -------------------------------------------
__global__ void k_detect(const int* __restrict__ ei32) {
    __shared__ int ok;
    if (threadIdx.x == 0) ok = 1;
    __syncthreads();
    if (ei32[2 * threadIdx.x + 1] != 0) ok = 0;
    __syncthreads();
    if (threadIdx.x == 0) g_is64 = ok;
}

// ---------------- graph preprocessing ---------------------------------------
__global__ void k_zero_deg() {
    int i = blockIdx.x * blockDim.x + threadIdx.x;
    if (i < NN) g_deg[i] = 0;
}

__global__ void k_edges(const void* __restrict__ eiv) {
    int e = blockIdx.x * blockDim.x + threadIdx.x;
    if (e >= EE) return;
    int r, c;
    if (g_is64) {
        const long long* ei = (const long long*)eiv;
        r = (int)ei[e];
        c = (int)ei[EE + e];
    } else {
        const int* ei = (const int*)eiv;
        r = ei[e];
        c = ei[EE + e];
    }
    if ((unsigned)r >= NN) r = 0;
    if ((unsigned)c >= NN) c = 0;
    g_row[e] = r;
    g_col[e] = c;
    if (r != c) atomicAdd(&g_deg[r], 1);
}

// chunked exclusive scan of g_deg into g_indptr (chunk = 512)
__global__ void k_scan1() {
    __shared__ int s[512];
    int i = blockIdx.x * 512 + threadIdx.x;
    int v = (i < NN) ? g_deg[i] : 0;
    s[threadIdx.x] = v;
    __syncthreads();
    for (int off = 1; off < 512; off <<= 1) {
        int t = 0;
        if (threadIdx.x >= off) t = s[threadIdx.x - off];
        __syncthreads();
        if (threadIdx.x >= off) s[threadIdx.x] += t;
        __syncthreads();
    }
    if (i < NN) g_indptr[i] = s[threadIdx.x] - v;
    if (threadIdx.x == 511) g_partials[blockIdx.x] = s[511];
}

__global__ void k_scan2(int nb) {
    __shared__ int s[512];
    int v = (threadIdx.x < nb) ? g_partials[threadIdx.x] : 0;
    s[threadIdx.x] = v;
    __syncthreads();
    for (int off = 1; off < 512; off <<= 1) {
        int t = 0;
        if (threadIdx.x >= off) t = s[threadIdx.x - off];
        __syncthreads();
        if (threadIdx.x >= off) s[threadIdx.x] += t;
        __syncthreads();
    }
    if (threadIdx.x < nb) g_partials[threadIdx.x] = s[threadIdx.x] - v;
    if (threadIdx.x == 511) g_indptr[NN] = s[511];
}

// scan finalize + dinv (merged)
__global__ void k_scan3() {
    int i = blockIdx.x * blockDim.x + threadIdx.x;
    if (i < NN) {
        int p = g_indptr[i] + g_partials[i >> 9];
        g_indptr[i] = p;
        g_pos[i] = p;
        int d = g_deg[i];
        g_dinv[i] = (d > 0) ? rsqrtf((float)d) : 0.f;
    }
}

// fill CSR + pad x into layer-1 slot 0 (merged; disjoint block ranges)
__global__ void k_fillpad(const float* __restrict__ x, int blocksE) {
    if ((int)blockIdx.x < blocksE) {
        int e = blockIdx.x * blockDim.x + threadIdx.x;
        if (e >= EE) return;
        int r = g_row[e];
        int c = g_col[e];
        if (r != c) {
            int p = atomicAdd(&g_pos[r], 1);
            int2 pk;
            pk.x = c;
            pk.y = __float_as_int(-g_dinv[r] * g_dinv[c]);
            g_ecsr[p] = pk;
        }
    } else {
        int i = (blockIdx.x - blocksE) * blockDim.x + threadIdx.x;
        if (i >= NN) return;
        float a = x[3 * i + 0];
        float b = x[3 * i + 1];
        float c = x[3 * i + 2];
        float4 t; t.x = a; t.y = b; t.z = c; t.w = 0.f;
        ((float4*)g_tx1all)[i] = t;
        g_tx1h[i] = pack4h(a, b, c, 0.f);
    }
}

// ---------------- layer 1 (F=3, fp16x4 gather), warp per node ---------------
__global__ void k_l1_spmv(int ksrc, int kdst, int ktx0) {
    int gw   = (blockIdx.x * blockDim.x + threadIdx.x) >> 5;
    int lane = threadIdx.x & 31;
    if (gw >= NN) return;
    const uint2* vh = g_tx1h + (size_t)ksrc * NN;
    int s = g_indptr[gw];
    int e = g_indptr[gw + 1];
    float ax = 0.f, ay = 0.f, az = 0.f;
    for (int base = s; base < e; base += 32) {
        int j = base + lane;
        int c = 0; float w = 0.f;
        if (j < e) {
            int2 p = __ldg(&g_ecsr[j]);
            c = p.x;
            w = __int_as_float(p.y);
        }
        uint2 hv = __ldg(&vh[c]);
        float2 f01 = __half22float2(*reinterpret_cast<__half2*>(&hv.x));
        float2 f23 = __half22float2(*reinterpret_cast<__half2*>(&hv.y));
        ax = fmaf(w, f01.x, ax);
        ay = fmaf(w, f01.y, ay);
        az = fmaf(w, f23.x, az);
    }
#pragma unroll
    for (int off = 16; off; off >>= 1) {
        ax += __shfl_xor_sync(FULLMASK, ax, off);
        ay += __shfl_xor_sync(FULLMASK, ay, off);
        az += __shfl_xor_sync(FULLMASK, az, off);
    }
    if (lane == 0) {
        float4* all = (float4*)g_tx1all;
        if (ktx0 >= 0) {
            float4 t0 = all[(size_t)ktx0 * NN + gw];
            ax = 2.f * ax - t0.x;
            ay = 2.f * ay - t0.y;
            az = 2.f * az - t0.z;
        }
        float4 r; r.x = ax; r.y = ay; r.z = az; r.w = 0.f;
        all[(size_t)kdst * NN + gw] = r;
        g_tx1h[(size_t)kdst * NN + gw] = pack4h(ax, ay, az, 0.f);
    }
}

// out[i][c] = silu( b1[c] + sum_{k,f} TxAll[k][i][f] * W1[k][f][c] )
__global__ void k_l1_gemm(const float* __restrict__ W1, const float* __restrict__ b1,
                          int outsel) {
    __shared__ float Ws[24 * 96];
    for (int t = threadIdx.x; t < 24 * 96; t += blockDim.x) Ws[t] = W1[t];
    __syncthreads();
    int gw   = (blockIdx.x * blockDim.x + threadIdx.x) >> 5;
    int lane = threadIdx.x & 31;
    if (gw >= NN) return;
    const float4* all = (const float4*)g_tx1all;
    float acc = b1[lane];
#pragma unroll
    for (int k = 0; k < 24; k++) {
        float4 t = all[(size_t)k * NN + gw];
        acc = fmaf(t.x, Ws[k * 96 + 0  + lane], acc);
        acc = fmaf(t.y, Ws[k * 96 + 32 + lane], acc);
        acc = fmaf(t.z, Ws[k * 96 + 64 + lane], acc);
    }
    float r = silu(acc);
    selbuf(outsel)[gw * 32 + lane] = r;
    sel16(outsel)[gw * 32 + lane] = __float2half(r);
}

// ---------------- F=32 layers ------------------------------------------------
// pair gather: 2 edges per warp; lane l covers feature-pair (l&15) of edge
// j + (l>>4). One LDG.32 per iteration serves 2 edges. Returns per-lane value
// for feature == lane.
__device__ __forceinline__ float gatherpair(const __half2* __restrict__ v2,
                                            int s, int e, int lane) {
    int   ehalf = lane >> 4;
    int   fp    = lane & 15;
    float accx = 0.f, accy = 0.f;
#pragma unroll 4
    for (int j2 = s; j2 < e; j2 += 2) {
        int j = j2 + ehalf;
        int c = 0; float w = 0.f;
        if (j < e) {
            int2 p = __ldg(&g_ecsr[j]);
            c = p.x;
            w = __int_as_float(p.y);
        }
        float2 f = __half22float2(__ldg(&v2[c * 16 + fp]));
        accx = fmaf(w, f.x, accx);
        accy = fmaf(w, f.y, accy);
    }
    accx += __shfl_xor_sync(FULLMASK, accx, 16);
    accy += __shfl_xor_sync(FULLMASK, accy, 16);
    // redistribute: lane = output feature f; source pair lane = f>>1
    float ex = __shfl_sync(FULLMASK, accx, lane >> 1);
    float ey = __shfl_sync(FULLMASK, accy, lane >> 1);
    return (lane & 1) ? ey : ex;
}

// first step of a layer: o = b + h@W0 + Tx1@W1, Tx1 = L(h) stored to dst(+fp16)
__global__ void k_spmv32_first(const float* __restrict__ W, const float* __restrict__ b,
                               int hsel, int dstsel, int outsel) {
    __shared__ float Ws0[1024];
    __shared__ float Ws1[1024];
    for (int t = threadIdx.x; t < 1024; t += blockDim.x) {
        Ws0[t] = W[t];
        Ws1[t] = W[1024 + t];
    }
    __syncthreads();
    int gw   = (blockIdx.x * blockDim.x + threadIdx.x) >> 5;
    int lane = threadIdx.x & 31;
    if (gw >= NN) return;
    float hv = selbuf(hsel)[gw * 32 + lane];
    float o  = b[lane];
#pragma unroll
    for (int f = 0; f < 32; f++)
        o = fmaf(__shfl_sync(FULLMASK, hv, f), Ws0[f * 32 + lane], o);
    float tx = gatherpair((const __half2*)sel16(hsel),
                          g_indptr[gw], g_indptr[gw + 1], lane);
    selbuf(dstsel)[gw * 32 + lane] = tx;
    sel16(dstsel)[gw * 32 + lane] = __float2half(tx);
#pragma unroll
    for (int f = 0; f < 32; f++)
        o = fmaf(__shfl_sync(FULLMASK, tx, f), Ws1[f * 32 + lane], o);
    selbuf(outsel)[gw * 32 + lane] = o;
}

// step k>=2: tx = 2 L(v) - tx0; opt store tx(+fp16); o += tx@Wk; opt silu(+fp16)
__global__ void k_spmv32(const float* __restrict__ Wk,
                         int vsel, int tx0sel, int dstsel, int outsel, int dosilu) {
    __shared__ float Ws[1024];
    for (int t = threadIdx.x; t < 1024; t += blockDim.x) Ws[t] = Wk[t];
    __syncthreads();
    int gw   = (blockIdx.x * blockDim.x + threadIdx.x) >> 5;
    int lane = threadIdx.x & 31;
    if (gw >= NN) return;
    float acc = gatherpair((const __half2*)sel16(vsel),
                           g_indptr[gw], g_indptr[gw + 1], lane);
    float tx  = 2.f * acc - selbuf(tx0sel)[gw * 32 + lane];
    if (dstsel >= 0) {
        selbuf(dstsel)[gw * 32 + lane] = tx;
        sel16(dstsel)[gw * 32 + lane] = __float2half(tx);
    }
    float o = selbuf(outsel)[gw * 32 + lane];
#pragma unroll
    for (int f = 0; f < 32; f++)
        o = fmaf(__shfl_sync(FULLMASK, tx, f), Ws[f * 32 + lane], o);
    if (dosilu) {
        o = silu(o);
        sel16(outsel)[gw * 32 + lane] = __float2half(o);
    }
    selbuf(outsel)[gw * 32 + lane] = o;
}

// layer 4: K=1, no bias: d_out[i] = sum_f h[i][f] * W4[f]
__global__ void k_final(const float* __restrict__ W4, int hsel, float* __restrict__ dout) {
    int gw   = (blockIdx.x * blockDim.x + threadIdx.x) >> 5;
    int lane = threadIdx.x & 31;
    if (gw >= NN) return;
    float p = selbuf(hsel)[gw * 32 + lane] * W4[lane];
#pragma unroll
    for (int off = 16; off; off >>= 1) p += __shfl_xor_sync(FULLMASK, p, off);
    if (lane == 0) dout[gw] = p;
}

// ---------------- host orchestration ----------------------------------------
static void layer32(const float* W, const float* b, int hsel, int outsel,
                    int s1, int s2, int K, int blocksWarp) {
    k_spmv32_first<<<blocksWarp, 256>>>(W, b, hsel, s1, outsel);
    int p0 = hsel, p1 = s1, f = s2;
    for (int k = 2; k < K; k++) {
        int last = (k == K - 1);
        k_spmv32<<<blocksWarp, 256>>>(W + (size_t)k * 1024, p1, p0,
                                      last ? -1 : f, outsel, last);
        int np0 = p1, np1 = f, nf = p0;
        p0 = np0; p1 = np1; f = nf;
    }
}

extern "C" void kernel_launch(void* const* d_in, const int* in_sizes, int n_in,
                              void* d_out, int out_size) {
    const float* x  = (const float*)d_in[0];
    const void*  ei = d_in[1];
    const float* W1 = (const float*)d_in[4];
    const float* b1 = (const float*)d_in[5];
    const float* W2 = (const float*)d_in[6];
    const float* b2 = (const float*)d_in[7];
    const float* W3 = (const float*)d_in[8];
    const float* b3 = (const float*)d_in[9];
    const float* W4 = (const float*)d_in[10];
    float* out = (float*)d_out;

    const int blocksN    = (NN + 255) / 256;
    const int blocksE    = (EE + 255) / 256;
    const int blocksScan = (NN + 511) / 512;
    const int blocksWarp = (NN * 32 + 255) / 256;

    // --- dtype probe + CSR build ---
    k_detect<<<1, 512>>>((const int*)ei);
    k_zero_deg<<<blocksN, 256>>>();
    k_edges<<<blocksE, 256>>>(ei);
    k_scan1<<<blocksScan, 512>>>();
    k_scan2<<<1, 512>>>(blocksScan);
    k_scan3<<<blocksN, 256>>>();
    k_fillpad<<<blocksE + blocksN, 256>>>(x, blocksE);

    // --- layer 1: K=24, 3 -> 32, silu ---
    k_l1_spmv<<<blocksWarp, 256>>>(0, 1, -1);
    for (int k = 2; k < 24; k++)
        k_l1_spmv<<<blocksWarp, 256>>>(k - 1, k, k - 2);
    k_l1_gemm<<<blocksWarp, 256>>>(W1, b1, /*outsel=*/0);   // h1 -> bufA (+fp16)

    // --- layer 2: K=12 ---
    layer32(W2, b2, 0, 1, 2, 3, 12, blocksWarp);            // h2 -> bufB (+fp16)

    // --- layer 3: K=10 ---
    layer32(W3, b3, 1, 0, 2, 3, 10, blocksWarp);            // h3 -> bufA (+fp16)

    // --- layer 4: K=1, 32 -> 1, no bias ---
    k_final<<<blocksWarp, 256>>>(W4, 0, out);

    (void)in_sizes; (void)n_in; (void)out_size;
}

// round 7
// speedup vs baseline: 1.2729x; 1.0499x over previous
#include <cuda_runtime.h>
#include <cuda_fp16.h>
#include <cstdint>

#define NN 100000
#define EE 3200000
#define FC 32
#define FULLMASK 0xFFFFFFFFu

// ---------------- scratch (device globals; no allocation anywhere) ----------
__device__ int   g_is64;
__device__ int   g_row[EE];
__device__ int   g_col[EE];
__device__ int   g_deg[NN];
__device__ float g_dinv[NN];
__device__ int   g_indptr[NN + 1];
__device__ int   g_pos[NN];
__device__ int2  g_ecsr[EE];          // packed {col, float_bits(weight)}
__device__ int   g_partials[512];

__device__ float g_tx1all[24 * NN * 4];   // layer1 basis fp32, float4-padded
__device__ uint2 g_tx1h[24 * NN];         // layer1 basis fp16x4 mirror (gather operand)
__device__ float  g_bufA[NN * FC];
__device__ float  g_bufB[NN * FC];
__device__ float  g_bufC[NN * FC];
__device__ float  g_bufD[NN * FC];
__device__ __half g_h16A[NN * FC];        // fp16 mirrors (gather operands)
__device__ __half g_h16B[NN * FC];
__device__ __half g_h16C[NN * FC];
__device__ __half g_h16D[NN * FC];

__device__ __forceinline__ float* selbuf(int s) {
    switch (s) {
        case 0:  return g_bufA;
        case 1:  return g_bufB;
        case 2:  return g_bufC;
        default: return g_bufD;
    }
}
__device__ __forceinline__ __half* sel16(int s) {
    switch (s) {
        case 0:  return g_h16A;
        case 1:  return g_h16B;
        case 2:  return g_h16C;
        default: return g_h16D;
    }
}

__device__ __forceinline__ float silu(float x) {
    return x / (1.f + __expf(-x));
}

__device__ __forceinline__ uint2 pack4h(float a, float b, float c, float d) {
    __half2 lo = __floats2half2_rn(a, b);
    __half2 hi = __floats2half2_rn(c, d);
    uint2 r;
    r.x = *reinterpret_cast<unsigned*>(&lo);
    r.y = *reinterpret_cast<unsigned*>(&hi);
    return r;
}

// ---------------- dtype detection -------------------------------------------
__global__ void k_detect(const int* __restrict__ ei32) {
    __shared__ int ok;
    if (threadIdx.x == 0) ok = 1;
    __syncthreads();
    if (ei32[2 * threadIdx.x + 1] != 0) ok = 0;
    __syncthreads();
    if (threadIdx.x == 0) g_is64 = ok;
}

// ---------------- graph preprocessing ---------------------------------------
__global__ void k_zero_deg() {
    int i = blockIdx.x * blockDim.x + threadIdx.x;
    if (i < NN) g_deg[i] = 0;
}

__global__ void k_edges(const void* __restrict__ eiv) {
    int e = blockIdx.x * blockDim.x + threadIdx.x;
    if (e >= EE) return;
    int r, c;
    if (g_is64) {
        const long long* ei = (const long long*)eiv;
        r = (int)ei[e];
        c = (int)ei[EE + e];
    } else {
        const int* ei = (const int*)eiv;
        r = ei[e];
        c = ei[EE + e];
    }
    if ((unsigned)r >= NN) r = 0;
    if ((unsigned)c >= NN) c = 0;
    g_row[e] = r;
    g_col[e] = c;
    if (r != c) atomicAdd(&g_deg[r], 1);
}

// chunked exclusive scan of g_deg into g_indptr (chunk = 512)
__global__ void k_scan1() {
    __shared__ int s[512];
    int i = blockIdx.x * 512 + threadIdx.x;
    int v = (i < NN) ? g_deg[i] : 0;
    s[threadIdx.x] = v;
    __syncthreads();
    for (int off = 1; off < 512; off <<= 1) {
        int t = 0;
        if (threadIdx.x >= off) t = s[threadIdx.x - off];
        __syncthreads();
        if (threadIdx.x >= off) s[threadIdx.x] += t;
        __syncthreads();
    }
    if (i < NN) g_indptr[i] = s[threadIdx.x] - v;
    if (threadIdx.x == 511) g_partials[blockIdx.x] = s[511];
}

__global__ void k_scan2(int nb) {
    __shared__ int s[512];
    int v = (threadIdx.x < nb) ? g_partials[threadIdx.x] : 0;
    s[threadIdx.x] = v;
    __syncthreads();
    for (int off = 1; off < 512; off <<= 1) {
        int t = 0;
        if (threadIdx.x >= off) t = s[threadIdx.x - off];
        __syncthreads();
        if (threadIdx.x >= off) s[threadIdx.x] += t;
        __syncthreads();
    }
    if (threadIdx.x < nb) g_partials[threadIdx.x] = s[threadIdx.x] - v;
    if (threadIdx.x == 511) g_indptr[NN] = s[511];
}

// scan finalize + dinv (merged)
__global__ void k_scan3() {
    int i = blockIdx.x * blockDim.x + threadIdx.x;
    if (i < NN) {
        int p = g_indptr[i] + g_partials[i >> 9];
        g_indptr[i] = p;
        g_pos[i] = p;
        int d = g_deg[i];
        g_dinv[i] = (d > 0) ? rsqrtf((float)d) : 0.f;
    }
}

// fill CSR + pad x into layer-1 slot 0 (merged; disjoint block ranges)
__global__ void k_fillpad(const float* __restrict__ x, int blocksE) {
    if ((int)blockIdx.x < blocksE) {
        int e = blockIdx.x * blockDim.x + threadIdx.x;
        if (e >= EE) return;
        int r = g_row[e];
        int c = g_col[e];
        if (r != c) {
            int p = atomicAdd(&g_pos[r], 1);
            int2 pk;
            pk.x = c;
            pk.y = __float_as_int(-g_dinv[r] * g_dinv[c]);
            g_ecsr[p] = pk;
        }
    } else {
        int i = (blockIdx.x - blocksE) * blockDim.x + threadIdx.x;
        if (i >= NN) return;
        float a = x[3 * i + 0];
        float b = x[3 * i + 1];
        float c = x[3 * i + 2];
        float4 t; t.x = a; t.y = b; t.z = c; t.w = 0.f;
        ((float4*)g_tx1all)[i] = t;
        g_tx1h[i] = pack4h(a, b, c, 0.f);
    }
}

// ---------------- layer 1 (F=3, fp16x4 gather), warp per node ---------------
__global__ void k_l1_spmv(int ksrc, int kdst, int ktx0) {
    int gw   = (blockIdx.x * blockDim.x + threadIdx.x) >> 5;
    int lane = threadIdx.x & 31;
    if (gw >= NN) return;
    const uint2* vh = g_tx1h + (size_t)ksrc * NN;
    int s = g_indptr[gw];
    int e = g_indptr[gw + 1];
    float ax = 0.f, ay = 0.f, az = 0.f;
    for (int base = s; base < e; base += 32) {
        int j = base + lane;
        int c = 0; float w = 0.f;
        if (j < e) {
            int2 p = __ldg(&g_ecsr[j]);
            c = p.x;
            w = __int_as_float(p.y);
        }
        uint2 hv = __ldg(&vh[c]);
        float2 f01 = __half22float2(*reinterpret_cast<__half2*>(&hv.x));
        float2 f23 = __half22float2(*reinterpret_cast<__half2*>(&hv.y));
        ax = fmaf(w, f01.x, ax);
        ay = fmaf(w, f01.y, ay);
        az = fmaf(w, f23.x, az);
    }
#pragma unroll
    for (int off = 16; off; off >>= 1) {
        ax += __shfl_xor_sync(FULLMASK, ax, off);
        ay += __shfl_xor_sync(FULLMASK, ay, off);
        az += __shfl_xor_sync(FULLMASK, az, off);
    }
    if (lane == 0) {
        float4* all = (float4*)g_tx1all;
        if (ktx0 >= 0) {
            float4 t0 = all[(size_t)ktx0 * NN + gw];
            ax = 2.f * ax - t0.x;
            ay = 2.f * ay - t0.y;
            az = 2.f * az - t0.z;
        }
        float4 r; r.x = ax; r.y = ay; r.z = az; r.w = 0.f;
        all[(size_t)kdst * NN + gw] = r;
        g_tx1h[(size_t)kdst * NN + gw] = pack4h(ax, ay, az, 0.f);
    }
}

// out[i][c] = silu( b1[c] + sum_{k,f} TxAll[k][i][f] * W1[k][f][c] )
__global__ void k_l1_gemm(const float* __restrict__ W1, const float* __restrict__ b1,
                          int outsel) {
    __shared__ float Ws[24 * 96];
    for (int t = threadIdx.x; t < 24 * 96; t += blockDim.x) Ws[t] = W1[t];
    __syncthreads();
    int gw   = (blockIdx.x * blockDim.x + threadIdx.x) >> 5;
    int lane = threadIdx.x & 31;
    if (gw >= NN) return;
    const float4* all = (const float4*)g_tx1all;
    float acc = b1[lane];
#pragma unroll
    for (int k = 0; k < 24; k++) {
        float4 t = all[(size_t)k * NN + gw];
        acc = fmaf(t.x, Ws[k * 96 + 0  + lane], acc);
        acc = fmaf(t.y, Ws[k * 96 + 32 + lane], acc);
        acc = fmaf(t.z, Ws[k * 96 + 64 + lane], acc);
    }
    float r = silu(acc);
    selbuf(outsel)[gw * 32 + lane] = r;
    sel16(outsel)[gw * 32 + lane] = __float2half(r);
}

// ---------------- F=32 layers ------------------------------------------------
// quad gather: 4 edges per warp-iteration; lane l loads feature-quad (l&7)
// of edge j + (l>>3) as one LDG.64. Returns per-lane value for feature == lane.
__device__ __forceinline__ float gatherquad(const uint2* __restrict__ v4,
                                            int s, int e, int lane) {
    int eslot = lane >> 3;     // 0..3: which of 4 edges this lane serves
    int q     = lane & 7;      // feature quad 0..7
    float a0 = 0.f, a1 = 0.f, a2 = 0.f, a3 = 0.f;
#pragma unroll 2
    for (int j4 = s; j4 < e; j4 += 4) {
        int j = j4 + eslot;
        int c = 0; float w = 0.f;
        if (j < e) {
            int2 p = __ldg(&g_ecsr[j]);
            c = p.x;
            w = __int_as_float(p.y);
        }
        uint2 hv = __ldg(&v4[c * 8 + q]);
        float2 f01 = __half22float2(*reinterpret_cast<__half2*>(&hv.x));
        float2 f23 = __half22float2(*reinterpret_cast<__half2*>(&hv.y));
        a0 = fmaf(w, f01.x, a0);
        a1 = fmaf(w, f01.y, a1);
        a2 = fmaf(w, f23.x, a2);
        a3 = fmaf(w, f23.y, a3);
    }
    // reduce across the 4 edge slots (lanes l, l^8, l^16, l^24)
    a0 += __shfl_xor_sync(FULLMASK, a0, 8);
    a1 += __shfl_xor_sync(FULLMASK, a1, 8);
    a2 += __shfl_xor_sync(FULLMASK, a2, 8);
    a3 += __shfl_xor_sync(FULLMASK, a3, 8);
    a0 += __shfl_xor_sync(FULLMASK, a0, 16);
    a1 += __shfl_xor_sync(FULLMASK, a1, 16);
    a2 += __shfl_xor_sync(FULLMASK, a2, 16);
    a3 += __shfl_xor_sync(FULLMASK, a3, 16);
    // redistribute: output lane f wants feature f = 4*(f>>2) + (f&3),
    // held by lane (f>>2) in component (f&3)
    int src = lane >> 2;
    float e0 = __shfl_sync(FULLMASK, a0, src);
    float e1 = __shfl_sync(FULLMASK, a1, src);
    float e2 = __shfl_sync(FULLMASK, a2, src);
    float e3 = __shfl_sync(FULLMASK, a3, src);
    int r = lane & 3;
    float lo = (r & 1) ? e1 : e0;
    float hi = (r & 1) ? e3 : e2;
    return (r & 2) ? hi : lo;
}

// first step of a layer: o = b + h@W0 + Tx1@W1, Tx1 = L(h) stored to dst(+fp16)
__global__ void k_spmv32_first(const float* __restrict__ W, const float* __restrict__ b,
                               int hsel, int dstsel, int outsel) {
    __shared__ float Ws0[1024];
    __shared__ float Ws1[1024];
    for (int t = threadIdx.x; t < 1024; t += blockDim.x) {
        Ws0[t] = W[t];
        Ws1[t] = W[1024 + t];
    }
    __syncthreads();
    int gw   = (blockIdx.x * blockDim.x + threadIdx.x) >> 5;
    int lane = threadIdx.x & 31;
    if (gw >= NN) return;
    float hv = selbuf(hsel)[gw * 32 + lane];
    float o  = b[lane];
#pragma unroll
    for (int f = 0; f < 32; f++)
        o = fmaf(__shfl_sync(FULLMASK, hv, f), Ws0[f * 32 + lane], o);
    float tx = gatherquad((const uint2*)sel16(hsel),
                          g_indptr[gw], g_indptr[gw + 1], lane);
    selbuf(dstsel)[gw * 32 + lane] = tx;
    sel16(dstsel)[gw * 32 + lane] = __float2half(tx);
#pragma unroll
    for (int f = 0; f < 32; f++)
        o = fmaf(__shfl_sync(FULLMASK, tx, f), Ws1[f * 32 + lane], o);
    selbuf(outsel)[gw * 32 + lane] = o;
}

// step k>=2: tx = 2 L(v) - tx0; opt store tx(+fp16); o += tx@Wk; opt silu(+fp16)
__global__ void k_spmv32(const float* __restrict__ Wk,
                         int vsel, int tx0sel, int dstsel, int outsel, int dosilu) {
    __shared__ float Ws[1024];
    for (int t = threadIdx.x; t < 1024; t += blockDim.x) Ws[t] = Wk[t];
    __syncthreads();
    int gw   = (blockIdx.x * blockDim.x + threadIdx.x) >> 5;
    int lane = threadIdx.x & 31;
    if (gw >= NN) return;
    float acc = gatherquad((const uint2*)sel16(vsel),
                           g_indptr[gw], g_indptr[gw + 1], lane);
    float tx  = 2.f * acc - selbuf(tx0sel)[gw * 32 + lane];
    if (dstsel >= 0) {
        selbuf(dstsel)[gw * 32 + lane] = tx;
        sel16(dstsel)[gw * 32 + lane] = __float2half(tx);
    }
    float o = selbuf(outsel)[gw * 32 + lane];
#pragma unroll
    for (int f = 0; f < 32; f++)
        o = fmaf(__shfl_sync(FULLMASK, tx, f), Ws[f * 32 + lane], o);
    if (dosilu) {
        o = silu(o);
        sel16(outsel)[gw * 32 + lane] = __float2half(o);
    }
    selbuf(outsel)[gw * 32 + lane] = o;
}

// layer 4: K=1, no bias: d_out[i] = sum_f h[i][f] * W4[f]
__global__ void k_final(const float* __restrict__ W4, int hsel, float* __restrict__ dout) {
    int gw   = (blockIdx.x * blockDim.x + threadIdx.x) >> 5;
    int lane = threadIdx.x & 31;
    if (gw >= NN) return;
    float p = selbuf(hsel)[gw * 32 + lane] * W4[lane];
#pragma unroll
    for (int off = 16; off; off >>= 1) p += __shfl_xor_sync(FULLMASK, p, off);
    if (lane == 0) dout[gw] = p;
}

// ---------------- host orchestration ----------------------------------------
static void layer32(const float* W, const float* b, int hsel, int outsel,
                    int s1, int s2, int K, int blocksWarp) {
    k_spmv32_first<<<blocksWarp, 256>>>(W, b, hsel, s1, outsel);
    int p0 = hsel, p1 = s1, f = s2;
    for (int k = 2; k < K; k++) {
        int last = (k == K - 1);
        k_spmv32<<<blocksWarp, 256>>>(W + (size_t)k * 1024, p1, p0,
                                      last ? -1 : f, outsel, last);
        int np0 = p1, np1 = f, nf = p0;
        p0 = np0; p1 = np1; f = nf;
    }
}

extern "C" void kernel_launch(void* const* d_in, const int* in_sizes, int n_in,
                              void* d_out, int out_size) {
    const float* x  = (const float*)d_in[0];
    const void*  ei = d_in[1];
    const float* W1 = (const float*)d_in[4];
    const float* b1 = (const float*)d_in[5];
    const float* W2 = (const float*)d_in[6];
    const float* b2 = (const float*)d_in[7];
    const float* W3 = (const float*)d_in[8];
    const float* b3 = (const float*)d_in[9];
    const float* W4 = (const float*)d_in[10];
    float* out = (float*)d_out;

    const int blocksN    = (NN + 255) / 256;
    const int blocksE    = (EE + 255) / 256;
    const int blocksScan = (NN + 511) / 512;
    const int blocksWarp = (NN * 32 + 255) / 256;

    // --- dtype probe + CSR build ---
    k_detect<<<1, 512>>>((const int*)ei);
    k_zero_deg<<<blocksN, 256>>>();
    k_edges<<<blocksE, 256>>>(ei);
    k_scan1<<<blocksScan, 512>>>();
    k_scan2<<<1, 512>>>(blocksScan);
    k_scan3<<<blocksN, 256>>>();
    k_fillpad<<<blocksE + blocksN, 256>>>(x, blocksE);

    // --- layer 1: K=24, 3 -> 32, silu ---
    k_l1_spmv<<<blocksWarp, 256>>>(0, 1, -1);
    for (int k = 2; k < 24; k++)
        k_l1_spmv<<<blocksWarp, 256>>>(k - 1, k, k - 2);
    k_l1_gemm<<<blocksWarp, 256>>>(W1, b1, /*outsel=*/0);   // h1 -> bufA (+fp16)

    // --- layer 2: K=12 ---
    layer32(W2, b2, 0, 1, 2, 3, 12, blocksWarp);            // h2 -> bufB (+fp16)

    // --- layer 3: K=10 ---
    layer32(W3, b3, 1, 0, 2, 3, 10, blocksWarp);            // h3 -> bufA (+fp16)

    // --- layer 4: K=1, 32 -> 1, no bias ---
    k_final<<<blocksWarp, 256>>>(W4, 0, out);

    (void)in_sizes; (void)n_in; (void)out_size;
}